// round 15
// baseline (speedup 1.0000x reference)
#include <cuda_runtime.h>
#include <cuda_bf16.h>
#include <cuda_fp16.h>
#include <math.h>
#include <cstdint>

typedef unsigned long long u64;
typedef unsigned int u32;

#define HEADS 8
#define NDIM  256
#define INNER 512
#define NTOKS 4096
#define BATCH 8
#define MTOT  (BATCH * NTOKS)   // 32768
#define NSPLIT 16
#define PL ((size_t)64 * 4096 * 64)   // one fp16 plane: [b*8+h][t][64]

// ---------------- scratch (device globals: allocation-guard safe) ----------------
__device__ __half g_kvs [(size_t)2 * PL];            // plane 0: k~, plane 1: v~ (fp16)
__device__ float g_dotp[(size_t)64 * NSPLIT * 64 * 64];
__device__ __half g_z2  [(size_t)MTOT * 256];        // z fp16
__device__ __half g_x2  [(size_t)MTOT * 256];
__device__ __half g_wkv2[(size_t)1024 * 256];        // Wkv^T fp16
__device__ __half g_wq2 [(size_t)512 * 256];         // Wq^T fp16
__device__ __half g_q2  [(size_t)MTOT * 512];        // q rot fp16 [M, INNER]
__device__ __half g_w2s [(size_t)BATCH * 256 * 512]; // W2^T fp16

// ---------------- MMA / async helpers ----------------
__device__ __forceinline__ u32 smem_u32(const void* p) {
    u32 a; asm("{ .reg .u64 t; cvta.to.shared.u64 t, %1; cvt.u32.u64 %0, t; }" : "=r"(a) : "l"(p));
    return a;
}
__device__ __forceinline__ void cpa16(u32 dst, const void* src) {
    asm volatile("cp.async.cg.shared.global [%0], [%1], 16;" :: "r"(dst), "l"(src));
}
#define CP_COMMIT() asm volatile("cp.async.commit_group;" ::: "memory")
#define CP_WAIT(n)  asm volatile("cp.async.wait_group %0;" :: "n"(n) : "memory")

__device__ __forceinline__ void ldsm4(u32* r, u32 a) {
    asm volatile("ldmatrix.sync.aligned.m8n8.x4.shared.b16 {%0,%1,%2,%3}, [%4];"
        : "=r"(r[0]), "=r"(r[1]), "=r"(r[2]), "=r"(r[3]) : "r"(a));
}
__device__ __forceinline__ void ldsm4t(u32* r, u32 a) {
    asm volatile("ldmatrix.sync.aligned.m8n8.x4.trans.shared.b16 {%0,%1,%2,%3}, [%4];"
        : "=r"(r[0]), "=r"(r[1]), "=r"(r[2]), "=r"(r[3]) : "r"(a));
}
__device__ __forceinline__ void mma16816h(float* c, const u32* a, const u32* b) {
    asm volatile("mma.sync.aligned.m16n8k16.row.col.f32.f16.f16.f32 "
        "{%0,%1,%2,%3}, {%4,%5,%6,%7}, {%8,%9}, {%0,%1,%2,%3};"
        : "+f"(c[0]), "+f"(c[1]), "+f"(c[2]), "+f"(c[3])
        : "r"(a[0]), "r"(a[1]), "r"(a[2]), "r"(a[3]), "r"(b[0]), "r"(b[1]));
}

// ---------------- f32x2 helpers ----------------
__device__ __forceinline__ u64 pack2(float x, float y) {
    u64 r; asm("mov.b64 %0, {%1,%2};" : "=l"(r) : "f"(x), "f"(y)); return r;
}
__device__ __forceinline__ u64 ffma2(u64 a, u64 b, u64 c) {
    u64 d; asm("fma.rn.f32x2 %0, %1, %2, %3;" : "=l"(d) : "l"(a), "l"(b), "l"(c)); return d;
}
__device__ __forceinline__ void unpack2(u64 v, float& x, float& y) {
    asm("mov.b64 {%0,%1}, %2;" : "=f"(x), "=f"(y) : "l"(v));
}

// ---------------- prep half: fp16-convert one data matrix + one transposed weight -------
// blocks [0,8192): data rows; [8192, 8192+nWblocks): weight cols.
__global__ void prep_part(const float* __restrict__ in, const float* __restrict__ W,
                          __half* __restrict__ out, __half* __restrict__ wout, int Nw) {
    const int bid = blockIdx.x, tid = threadIdx.x;
    if (bid < 8192) {
        size_t idx = (size_t)bid * 256 + tid;     // one float4
        float4 v = ((const float4*)in)[idx];
        __half2 p0 = __half2{__float2half_rn(v.x), __float2half_rn(v.y)};
        __half2 p1 = __half2{__float2half_rn(v.z), __float2half_rn(v.w)};
        __half2* dst = (__half2*)(out + idx * 4);
        dst[0] = p0; dst[1] = p1;
    } else {
        const int n = bid - 8192;
        wout[(size_t)n * 256 + tid] = __float2half_rn(W[(size_t)tid * Nw + n]);
    }
}

// ---------------- main GEMM (K2=256): bx<8 -> kv (norm+rot planes), bx>=8 -> q --------
#define ROWB 80
#define TILEB (128 * ROWB)
#define STAGEB (2 * TILEB)
#define NSTAGE 4
#define GSMEM (NSTAGE * STAGEB)

__global__ __launch_bounds__(256, 2) void gemm_main(
    const __half* __restrict__ z2, const __half* __restrict__ wkv2,
    const __half* __restrict__ x2, const __half* __restrict__ wq2,
    __half* __restrict__ Ckv, __half* __restrict__ Cq,
    const float* __restrict__ z_pos, const float* __restrict__ x_pos, int bx0)
{
    extern __shared__ __align__(1024) char smem[];
    const int bx = blockIdx.x + bx0;
    const int isKv = (bx < 8);
    const __half* A2 = isKv ? z2 : x2;
    const __half* B2 = isKv ? wkv2 : wq2;
    const int n0 = (isKv ? bx : bx - 8) * 128;
    const int m0 = blockIdx.y * 128;
    const int tid = threadIdx.x, lane = tid & 31, wid = tid >> 5;
    const int wr = wid >> 2, wc = wid & 3;
    const u32 sb = smem_u32(smem);

    const int K2 = 256, total = 8;
    const int lrow = tid >> 1;
    const int lcg = (tid & 1) * 2;

    float acc[4][4][4];
    #pragma unroll
    for (int i = 0; i < 4; i++)
        #pragma unroll
        for (int j = 0; j < 4; j++)
            #pragma unroll
            for (int r = 0; r < 4; r++) acc[i][j][r] = 0.f;

    auto issue = [&](int it) {
        const int stage = it & (NSTAGE - 1);
        const int kk = it * 32;
        const __half* as = A2 + (size_t)(m0 + lrow) * K2 + kk + lcg * 8;
        const __half* bs = B2 + (size_t)(n0 + lrow) * K2 + kk + lcg * 8;
        const u32 da = sb + stage * STAGEB + lrow * ROWB + lcg * 16;
        cpa16(da, as);              cpa16(da + 16, as + 8);
        cpa16(da + TILEB, bs);      cpa16(da + TILEB + 16, bs + 8);
        CP_COMMIT();
    };

    auto compute = [&](int stage) {
        const u32 ab = sb + stage * STAGEB;
        const u32 bb = ab + TILEB;
        #pragma unroll
        for (int kb = 0; kb < 2; kb++) {
            u32 a[4][4], b[2][4];
            #pragma unroll
            for (int mf = 0; mf < 4; mf++) {
                u32 addr = ab + (u32)(wr * 64 + mf * 16 + (lane & 15)) * ROWB
                              + kb * 32 + (lane >> 4) * 16;
                ldsm4(a[mf], addr);
            }
            #pragma unroll
            for (int nfp = 0; nfp < 2; nfp++) {
                u32 addr = bb + (u32)(wc * 32 + nfp * 16 + ((lane >> 4) << 3) + (lane & 7)) * ROWB
                              + kb * 32 + ((lane >> 3) & 1) * 16;
                ldsm4(b[nfp], addr);
            }
            #pragma unroll
            for (int mf = 0; mf < 4; mf++)
                #pragma unroll
                for (int nf = 0; nf < 4; nf++)
                    mma16816h(acc[mf][nf], a[mf], &b[nf >> 1][(nf & 1) * 2]);
        }
    };

    issue(0); issue(1); issue(2);
    for (int i = 0; i < total; i++) {
        if (i < total - 2)       CP_WAIT(2);
        else if (i == total - 2) CP_WAIT(1);
        else                     CP_WAIT(0);
        __syncthreads();
        compute(i & (NSTAGE - 1));
        if (i + 3 < total) issue(i + 3);
    }

    if (isKv) {
        __syncthreads();
        float* red = (float*)smem;
        float s8[8], q8[8], mean[8], inv[8];
        #pragma unroll
        for (int mf = 0; mf < 4; mf++)
            #pragma unroll
            for (int rb = 0; rb < 2; rb++) {
                const int ri = mf * 2 + rb;
                float s = 0.f, q = 0.f;
                #pragma unroll
                for (int nf = 0; nf < 4; nf++)
                    #pragma unroll
                    for (int cb = 0; cb < 2; cb++) {
                        float a = acc[mf][nf][rb * 2 + cb];
                        s += a; q += a * a;
                    }
                s += __shfl_xor_sync(0xffffffffu, s, 1); q += __shfl_xor_sync(0xffffffffu, q, 1);
                s += __shfl_xor_sync(0xffffffffu, s, 2); q += __shfl_xor_sync(0xffffffffu, q, 2);
                s8[ri] = s; q8[ri] = q;
            }
        if ((lane & 3) == 0) {
            #pragma unroll
            for (int ri = 0; ri < 8; ri++) {
                const int idx = (((wr * 4 + wc) * 8) + ri) * 8 + (lane >> 2);
                red[idx * 2] = s8[ri]; red[idx * 2 + 1] = q8[ri];
            }
        }
        __syncthreads();
        #pragma unroll
        for (int ri = 0; ri < 8; ri++) {
            const int idx = (((wr * 4 + (wc ^ 1)) * 8) + ri) * 8 + (lane >> 2);
            const float ts = s8[ri] + red[idx * 2];
            const float tq = q8[ri] + red[idx * 2 + 1];
            const float mu = ts * (1.f / 64.f);
            mean[ri] = mu;
            inv[ri] = rsqrtf(fmaxf(tq * (1.f / 64.f) - mu * mu, 0.f) + 1e-5f);
        }

        const int isK = (bx < 4);
        const int g = (isK ? bx : bx - 4) * 2 + (wc >> 1);
        const int half = wc & 1;
        const int lq = lane & 3;
        __half* base0 = Ckv + (isK ? 0 : PL);
        #pragma unroll
        for (int mf = 0; mf < 4; mf++)
            #pragma unroll
            for (int rb = 0; rb < 2; rb++) {
                const int ri = mf * 2 + rb;
                const int m = m0 + wr * 64 + mf * 16 + (lane >> 2) + rb * 8;
                const int bb = m >> 12, tt = m & 4095;
                const size_t rowoff = ((size_t)(bb * 8 + g) * 4096 + tt) * 64;
                const float mu = mean[ri], iv = inv[ri];
                if (isK) {
                    const float pp = z_pos[(size_t)m * 2 + half] * 64.f;
                    #pragma unroll
                    for (int nf2 = 0; nf2 < 2; nf2++) {
                        float o[4];
                        #pragma unroll
                        for (int cb = 0; cb < 2; cb++) {
                            const int j = nf2 * 8 + lq * 2 + cb;
                            const float invf = exp2f(-(float)j * (13.287712379549449f / 16.f));
                            float sn, co; sincosf(pp * invf, &sn, &co);
                            const float vlo = (acc[mf][nf2][rb * 2 + cb]     - mu) * iv;
                            const float vhi = (acc[mf][nf2 + 2][rb * 2 + cb] - mu) * iv;
                            o[cb]     = vlo * co - vhi * sn;
                            o[2 + cb] = vhi * co + vlo * sn;
                        }
                        const int cg = half * 32 + nf2 * 8 + lq * 2;
                        *(__half2*)&base0[rowoff + cg] =
                            __half2{__float2half_rn(o[0]), __float2half_rn(o[1])};
                        *(__half2*)&base0[rowoff + cg + 16] =
                            __half2{__float2half_rn(o[2]), __float2half_rn(o[3])};
                    }
                } else {
                    #pragma unroll
                    for (int nf = 0; nf < 4; nf++) {
                        const int cg = half * 32 + nf * 8 + lq * 2;
                        const float a0 = (acc[mf][nf][rb * 2]     - mu) * iv;
                        const float a1 = (acc[mf][nf][rb * 2 + 1] - mu) * iv;
                        *(__half2*)&base0[rowoff + cg] =
                            __half2{__float2half_rn(a0), __float2half_rn(a1)};
                    }
                }
            }
    } else {
        const int half = wc & 1;
        const int lq = lane & 3;
        #pragma unroll
        for (int mf = 0; mf < 4; mf++) {
            #pragma unroll
            for (int rb = 0; rb < 2; rb++) {
                const int r = m0 + wr * 64 + mf * 16 + (lane >> 2) + rb * 8;
                const float pp = x_pos[(size_t)r * 2 + half] * 64.f;
                const size_t rowb = (size_t)r * 512;
                #pragma unroll
                for (int nf2 = 0; nf2 < 2; nf2++) {
                    float o[4];
                    #pragma unroll
                    for (int cb = 0; cb < 2; cb++) {
                        const int j = nf2 * 8 + lq * 2 + cb;
                        const float invf = exp2f(-(float)j * (13.287712379549449f / 16.f));
                        float s, co; sincosf(pp * invf, &s, &co);
                        const int idx = rb * 2 + cb;
                        const float vlo = acc[mf][nf2][idx];
                        const float vhi = acc[mf][nf2 + 2][idx];
                        o[cb]     = vlo * co - vhi * s;
                        o[2 + cb] = vhi * co + vlo * s;
                    }
                    const int cg = n0 + wc * 32 + nf2 * 8 + lq * 2;
                    *(__half2*)&Cq[rowb + cg] =
                        __half2{__float2half_rn(o[0]), __float2half_rn(o[1])};
                    *(__half2*)&Cq[rowb + cg + 16] =
                        __half2{__float2half_rn(o[2]), __float2half_rn(o[3])};
                }
            }
        }
    }
}

// ---------------- epilogue GEMM: out[b] = q2[b] @ W2s[b]^T + bout ----------------------
__global__ __launch_bounds__(256, 2) void gemm_epi(
    const __half* __restrict__ A2, const __half* __restrict__ B2,
    float* __restrict__ C, const float* __restrict__ bias)
{
    extern __shared__ __align__(1024) char smem[];
    A2 += (size_t)blockIdx.z * ((long)NTOKS * 512);
    B2 += (size_t)blockIdx.z * ((long)256 * 512);
    C  += (size_t)blockIdx.z * ((long)NTOKS * 256);
    const int m0 = blockIdx.y * 128, n0 = blockIdx.x * 128;
    const int tid = threadIdx.x, lane = tid & 31, wid = tid >> 5;
    const int wr = wid >> 2, wc = wid & 3;
    const u32 sb = smem_u32(smem);

    const int K2 = 512, total = 16;
    const int lrow = tid >> 1;
    const int lcg = (tid & 1) * 2;

    float acc[4][4][4];
    #pragma unroll
    for (int i = 0; i < 4; i++)
        #pragma unroll
        for (int j = 0; j < 4; j++)
            #pragma unroll
            for (int r = 0; r < 4; r++) acc[i][j][r] = 0.f;

    auto issue = [&](int it) {
        const int stage = it & (NSTAGE - 1);
        const int kk = it * 32;
        const __half* as = A2 + (size_t)(m0 + lrow) * K2 + kk + lcg * 8;
        const __half* bs = B2 + (size_t)(n0 + lrow) * K2 + kk + lcg * 8;
        const u32 da = sb + stage * STAGEB + lrow * ROWB + lcg * 16;
        cpa16(da, as);              cpa16(da + 16, as + 8);
        cpa16(da + TILEB, bs);      cpa16(da + TILEB + 16, bs + 8);
        CP_COMMIT();
    };

    auto compute = [&](int stage) {
        const u32 ab = sb + stage * STAGEB;
        const u32 bb = ab + TILEB;
        #pragma unroll
        for (int kb = 0; kb < 2; kb++) {
            u32 a[4][4], b[2][4];
            #pragma unroll
            for (int mf = 0; mf < 4; mf++) {
                u32 addr = ab + (u32)(wr * 64 + mf * 16 + (lane & 15)) * ROWB
                              + kb * 32 + (lane >> 4) * 16;
                ldsm4(a[mf], addr);
            }
            #pragma unroll
            for (int nfp = 0; nfp < 2; nfp++) {
                u32 addr = bb + (u32)(wc * 32 + nfp * 16 + ((lane >> 4) << 3) + (lane & 7)) * ROWB
                              + kb * 32 + ((lane >> 3) & 1) * 16;
                ldsm4(b[nfp], addr);
            }
            #pragma unroll
            for (int mf = 0; mf < 4; mf++)
                #pragma unroll
                for (int nf = 0; nf < 4; nf++)
                    mma16816h(acc[mf][nf], a[mf], &b[nf >> 1][(nf & 1) * 2]);
        }
    };

    issue(0); issue(1); issue(2);
    for (int i = 0; i < total; i++) {
        if (i < total - 2)       CP_WAIT(2);
        else if (i == total - 2) CP_WAIT(1);
        else                     CP_WAIT(0);
        __syncthreads();
        compute(i & (NSTAGE - 1));
        if (i + 3 < total) issue(i + 3);
    }

    const int rbase = m0 + wr * 64 + (lane >> 2);
    const int cbase = n0 + wc * 32 + (lane & 3) * 2;
    #pragma unroll
    for (int nf = 0; nf < 4; nf++) {
        const int c = cbase + nf * 8;
        const float bx = bias[c], by = bias[c + 1];
        #pragma unroll
        for (int mf = 0; mf < 4; mf++) {
            const int r = rbase + mf * 16;
            *(float2*)&C[(size_t)r * 256 + c] =
                make_float2(acc[mf][nf][0] + bx, acc[mf][nf][1] + by);
            *(float2*)&C[(size_t)(r + 8) * 256 + c] =
                make_float2(acc[mf][nf][2] + bx, acc[mf][nf][3] + by);
        }
    }
}

// ---------------- dots: pure streaming fp16 Gram MMA ----------------
#define DROWB 144
#define DTILE (64 * DROWB)
#define DSTG2 (2 * DTILE)
#define DSM_BYTES (2 * DSTG2)

__global__ __launch_bounds__(256, 2) void dots_pure(const __half* __restrict__ kvs,
                                                    float* __restrict__ part) {
    extern __shared__ __align__(1024) char dsm[];
    const u32 sb = smem_u32(dsm);

    const int split = blockIdx.x;
    const int bh = blockIdx.y;
    const int tid = threadIdx.x;
    const int w = tid >> 5, lane = tid & 31;
    const int wr = w >> 1, wc = w & 1;

    float acc[4][4];
    #pragma unroll
    for (int i = 0; i < 4; i++)
        #pragma unroll
        for (int j = 0; j < 4; j++) acc[i][j] = 0.f;

    auto issue = [&](int c) {
        const int t0 = split * 256 + c * 64;
        const u32 sbase = sb + (c & 1) * DSTG2;
        #pragma unroll
        for (int i = 0; i < 4; i++) {
            const int idx = i * 256 + tid;
            const int plane = idx >> 9;
            const int r = (idx >> 3) & 63;
            const int seg = idx & 7;
            const __half* src = kvs + (size_t)plane * PL
                + ((size_t)bh * 4096 + t0 + r) * 64 + seg * 8;
            cpa16(sbase + plane * DTILE + r * DROWB + seg * 16, src);
        }
        CP_COMMIT();
    };

    issue(0);
    for (int c = 0; c < 4; c++) {
        if (c < 3) { issue(c + 1); CP_WAIT(1); } else { CP_WAIT(0); }
        __syncthreads();
        const u32 khb = sb + (c & 1) * DSTG2;
        const u32 vhb = khb + DTILE;
        #pragma unroll
        for (int kt = 0; kt < 4; kt++) {
            const u32 arow = (u32)(kt * 16 + (lane & 7) + ((lane >> 4) << 3));
            const u32 acol = (u32)(wr * 16 + ((lane >> 3) & 1) * 8);
            u32 ah[4];
            ldsm4t(ah, khb + arow * DROWB + acol * 2);
            const u32 brow = (u32)(kt * 16 + (lane & 7) + ((lane >> 3) & 1) * 8);
            const u32 bcol = (u32)(wc * 32 + ((lane >> 4) << 3));
            const u32 boff = brow * DROWB + bcol * 2;
            u32 bh0[4], bh1[4];
            ldsm4t(bh0, vhb + boff);
            ldsm4t(bh1, vhb + boff + 32);
            mma16816h(acc[0], ah, &bh0[0]);
            mma16816h(acc[1], ah, &bh0[2]);
            mma16816h(acc[2], ah, &bh1[0]);
            mma16816h(acc[3], ah, &bh1[2]);
        }
        __syncthreads();
    }

    float* dst = part + ((size_t)bh * NSPLIT + split) * 4096;
    const int dr = wr * 16 + (lane >> 2);
    const int ec = wc * 32 + (lane & 3) * 2;
    #pragma unroll
    for (int nf = 0; nf < 4; nf++) {
        *(float2*)&dst[(size_t)dr * 64 + ec + nf * 8]       = make_float2(acc[nf][0], acc[nf][1]);
        *(float2*)&dst[(size_t)(dr + 8) * 64 + ec + nf * 8] = make_float2(acc[nf][2], acc[nf][3]);
    }
}

// ---------------- w2k: W2s = fp16( ((sum dots)/n2 @ Wout)^T ), 4-wide LDG batching -----
__global__ __launch_bounds__(256) void w2k(const float* __restrict__ part, const float* __restrict__ Wout,
                                           __half* __restrict__ W2s) {
    const int bh = blockIdx.x, dg = blockIdx.y;
    const int b = bh >> 3, h = bh & 7;
    __shared__ float ds[512];                      // [8 d][64 e]
    const int tid = threadIdx.x;
    if (tid < 128) {
        float4 s = make_float4(0.f, 0.f, 0.f, 0.f);
        const float4* base = (const float4*)(part + (size_t)bh * NSPLIT * 4096 + dg * 512) + tid;
        #pragma unroll
        for (int sp = 0; sp < NSPLIT; sp++) {
            const float4 v = base[sp * 1024];
            s.x += v.x; s.y += v.y; s.z += v.z; s.w += v.w;
        }
        *(float4*)&ds[tid * 4] = make_float4(s.x * (1.f / 4096.f), s.y * (1.f / 4096.f),
                                             s.z * (1.f / 4096.f), s.w * (1.f / 4096.f));
    }
    __syncthreads();

    const int p = tid & 127, dq = tid >> 7;
    u64 acc[4];
    #pragma unroll
    for (int d = 0; d < 4; d++) acc[d] = 0ull;
    const float* wbase = Wout + (size_t)(h * 64) * 256 + 2 * p;
    #pragma unroll 2
    for (int e = 0; e < 64; e += 4) {
        const u64 w0 = *(const u64*)(wbase + (size_t)(e + 0) * 256);
        const u64 w1 = *(const u64*)(wbase + (size_t)(e + 1) * 256);
        const u64 w2 = *(const u64*)(wbase + (size_t)(e + 2) * 256);
        const u64 w3 = *(const u64*)(wbase + (size_t)(e + 3) * 256);
        const float* dsr = &ds[(dq * 4) * 64 + e];
        #pragma unroll
        for (int d = 0; d < 4; d++) {
            const float* r = dsr + d * 64;
            acc[d] = ffma2(pack2(r[0], r[0]), w0, acc[d]);
            acc[d] = ffma2(pack2(r[1], r[1]), w1, acc[d]);
            acc[d] = ffma2(pack2(r[2], r[2]), w2, acc[d]);
            acc[d] = ffma2(pack2(r[3], r[3]), w3, acc[d]);
        }
    }
    #pragma unroll
    for (int d = 0; d < 4; d++) {
        float o0, o1; unpack2(acc[d], o0, o1);
        const int dgg = h * 64 + dg * 8 + dq * 4 + d;
        size_t r0 = ((size_t)b * 256 + 2 * p) * 512;
        W2s[r0 + dgg]       = __float2half_rn(o0);
        W2s[r0 + 512 + dgg] = __float2half_rn(o1);
    }
}

// ---------------- launch ----------------
extern "C" void kernel_launch(void* const* d_in, const int* in_sizes, int n_in,
                              void* d_out, int out_size) {
    const float* x     = (const float*)d_in[0];
    const float* z     = (const float*)d_in[1];
    const float* x_pos = (const float*)d_in[2];
    const float* z_pos = (const float*)d_in[3];
    const float* Wq    = (const float*)d_in[4];
    const float* Wkv   = (const float*)d_in[5];
    const float* Wout  = (const float*)d_in[6];
    const float* bout  = (const float*)d_in[7];
    float* out = (float*)d_out;

    float* dotp;
    __half *kvs, *z2, *x2, *wkv2, *wq2, *q2, *w2s;
    cudaGetSymbolAddress((void**)&kvs,  g_kvs);
    cudaGetSymbolAddress((void**)&dotp, g_dotp);
    cudaGetSymbolAddress((void**)&z2,   g_z2);
    cudaGetSymbolAddress((void**)&x2,   g_x2);
    cudaGetSymbolAddress((void**)&wkv2, g_wkv2);
    cudaGetSymbolAddress((void**)&wq2,  g_wq2);
    cudaGetSymbolAddress((void**)&q2,   g_q2);
    cudaGetSymbolAddress((void**)&w2s,  g_w2s);

    // lazy one-time host resources (no device memory involved)
    static cudaStream_t s2 = nullptr;
    static cudaEvent_t evRoot = nullptr, evKV = nullptr, evQ = nullptr;
    if (!s2) {
        cudaStreamCreateWithFlags(&s2, cudaStreamNonBlocking);
        cudaEventCreateWithFlags(&evRoot, cudaEventDisableTiming);
        cudaEventCreateWithFlags(&evKV, cudaEventDisableTiming);
        cudaEventCreateWithFlags(&evQ, cudaEventDisableTiming);
        cudaFuncSetAttribute(gemm_main, cudaFuncAttributeMaxDynamicSharedMemorySize, GSMEM);
        cudaFuncSetAttribute(gemm_epi,  cudaFuncAttributeMaxDynamicSharedMemorySize, GSMEM);
        cudaFuncSetAttribute(dots_pure, cudaFuncAttributeMaxDynamicSharedMemorySize, DSM_BYTES);
    }

    // fork side stream; both prep halves run concurrently (memory-bound, share BW)
    cudaEventRecord(evRoot, 0);
    cudaStreamWaitEvent(s2, evRoot, 0);

    prep_part<<<9216, 256>>>(z, Wkv, z2, wkv2, 1024);          // main: z + Wkv
    prep_part<<<8704, 256, 0, s2>>>(x, Wq, x2, wq2, 512);      // side: x + Wq

    // kv GEMM on main stream (needs z2/wkv2 only)
    gemm_main<<<dim3(8, 256), 256, GSMEM>>>(z2, wkv2, x2, wq2, kvs, q2, z_pos, x_pos, 0);
    cudaEventRecord(evKV, 0);

    // q GEMM on side stream AFTER kv completes -> overlaps dots+w2k (different pipes)
    cudaStreamWaitEvent(s2, evKV, 0);
    gemm_main<<<dim3(4, 256), 256, GSMEM, s2>>>(z2, wkv2, x2, wq2, kvs, q2, z_pos, x_pos, 8);
    cudaEventRecord(evQ, s2);

    // dots + w2k on main stream (DRAM / latency bound; co-run with q GEMM)
    dots_pure<<<dim3(NSPLIT, 64), 256, DSM_BYTES>>>(kvs, dotp);
    w2k<<<dim3(64, 8), 256>>>(dotp, Wout, w2s);

    // join: epilogue needs q2 (side) + w2s (main)
    cudaStreamWaitEvent(0, evQ, 0);
    gemm_epi<<<dim3(2, 32, BATCH), 256, GSMEM>>>(q2, w2s, out, bout);
}

// round 16
// speedup vs baseline: 1.0632x; 1.0632x over previous
#include <cuda_runtime.h>
#include <cuda_bf16.h>
#include <cuda_fp16.h>
#include <math.h>
#include <cstdint>

typedef unsigned long long u64;
typedef unsigned int u32;

#define HEADS 8
#define NDIM  256
#define INNER 512
#define NTOKS 4096
#define BATCH 8
#define MTOT  (BATCH * NTOKS)   // 32768
#define NSPLIT 16
#define PL ((size_t)64 * 4096 * 64)   // one fp16 plane: [b*8+h][t][64]

// ---------------- scratch (device globals: allocation-guard safe) ----------------
__device__ __half g_kvs [(size_t)2 * PL];            // plane 0: k~, plane 1: v~ (fp16)
__device__ float g_dotp[(size_t)64 * NSPLIT * 64 * 64];
__device__ __half g_z2  [(size_t)MTOT * 256];        // z fp16
__device__ __half g_x2  [(size_t)MTOT * 256];
__device__ __half g_wkv2[(size_t)1024 * 256];        // Wkv^T fp16
__device__ __half g_wq2 [(size_t)512 * 256];         // Wq^T fp16
__device__ __half g_q2  [(size_t)MTOT * 512];        // q rot fp16 [M, INNER]
__device__ __half g_w2s [(size_t)BATCH * 256 * 512]; // W2^T fp16
__device__ float g_zrot[(size_t)MTOT * 64];          // rot table z: [tok][(cx,sx)x16,(cy,sy)x16]
__device__ float g_xrot[(size_t)MTOT * 64];          // rot table x

// ---------------- MMA / async helpers ----------------
__device__ __forceinline__ u32 smem_u32(const void* p) {
    u32 a; asm("{ .reg .u64 t; cvta.to.shared.u64 t, %1; cvt.u32.u64 %0, t; }" : "=r"(a) : "l"(p));
    return a;
}
__device__ __forceinline__ void cpa16(u32 dst, const void* src) {
    asm volatile("cp.async.cg.shared.global [%0], [%1], 16;" :: "r"(dst), "l"(src));
}
#define CP_COMMIT() asm volatile("cp.async.commit_group;" ::: "memory")
#define CP_WAIT(n)  asm volatile("cp.async.wait_group %0;" :: "n"(n) : "memory")

__device__ __forceinline__ void ldsm4(u32* r, u32 a) {
    asm volatile("ldmatrix.sync.aligned.m8n8.x4.shared.b16 {%0,%1,%2,%3}, [%4];"
        : "=r"(r[0]), "=r"(r[1]), "=r"(r[2]), "=r"(r[3]) : "r"(a));
}
__device__ __forceinline__ void ldsm4t(u32* r, u32 a) {
    asm volatile("ldmatrix.sync.aligned.m8n8.x4.trans.shared.b16 {%0,%1,%2,%3}, [%4];"
        : "=r"(r[0]), "=r"(r[1]), "=r"(r[2]), "=r"(r[3]) : "r"(a));
}
__device__ __forceinline__ void mma16816h(float* c, const u32* a, const u32* b) {
    asm volatile("mma.sync.aligned.m16n8k16.row.col.f32.f16.f16.f32 "
        "{%0,%1,%2,%3}, {%4,%5,%6,%7}, {%8,%9}, {%0,%1,%2,%3};"
        : "+f"(c[0]), "+f"(c[1]), "+f"(c[2]), "+f"(c[3])
        : "r"(a[0]), "r"(a[1]), "r"(a[2]), "r"(a[3]), "r"(b[0]), "r"(b[1]));
}

// ---------------- f32x2 helpers ----------------
__device__ __forceinline__ u64 pack2(float x, float y) {
    u64 r; asm("mov.b64 %0, {%1,%2};" : "=l"(r) : "f"(x), "f"(y)); return r;
}
__device__ __forceinline__ u64 ffma2(u64 a, u64 b, u64 c) {
    u64 d; asm("fma.rn.f32x2 %0, %1, %2, %3;" : "=l"(d) : "l"(a), "l"(b), "l"(c)); return d;
}
__device__ __forceinline__ void unpack2(u64 v, float& x, float& y) {
    asm("mov.b64 {%0,%1}, %2;" : "=f"(x), "=f"(y) : "l"(v));
}

// ---------------- prep: fp16 convert data + weight^T + rotary sincos table -------------
// blocks: [0,8192) data rows; [8192, 8192+Nw) weight cols; [8192+Nw, +2048) rot table.
__global__ void prep_part(const float* __restrict__ in, const float* __restrict__ W,
                          __half* __restrict__ out, __half* __restrict__ wout, int Nw,
                          const float* __restrict__ pos, float* __restrict__ rot) {
    const int bid = blockIdx.x, tid = threadIdx.x;
    if (bid < 8192) {
        size_t idx = (size_t)bid * 256 + tid;     // one float4
        float4 v = ((const float4*)in)[idx];
        __half2 p0 = __half2{__float2half_rn(v.x), __float2half_rn(v.y)};
        __half2 p1 = __half2{__float2half_rn(v.z), __float2half_rn(v.w)};
        __half2* dst = (__half2*)(out + idx * 4);
        dst[0] = p0; dst[1] = p1;
    } else if (bid < 8192 + Nw) {
        const int n = bid - 8192;
        wout[(size_t)n * 256 + tid] = __float2half_rn(W[(size_t)tid * Nw + n]);
    } else {
        const int bid_r = bid - 8192 - Nw;
        const int token = bid_r * 16 + (tid >> 4);
        const int j = tid & 15;
        const float px = pos[(size_t)token * 2]     * 64.f;
        const float py = pos[(size_t)token * 2 + 1] * 64.f;
        const float invf = exp2f(-(float)j * (13.287712379549449f / 16.f));
        float sx, cx, sy, cy;
        sincosf(px * invf, &sx, &cx);
        sincosf(py * invf, &sy, &cy);
        float2* r2 = (float2*)(rot + (size_t)token * 64);
        r2[j]      = make_float2(cx, sx);
        r2[16 + j] = make_float2(cy, sy);
    }
}

// ---------------- main GEMM (K2=256): bx<8 -> kv (norm+rot planes), bx>=8 -> q --------
#define ROWB 80
#define TILEB (128 * ROWB)
#define STAGEB (2 * TILEB)
#define NSTAGE 4
#define GSMEM (NSTAGE * STAGEB)
#define TSTRIDE 72   // floats per staged rot row (16B-aligned, 2-way max bank conflict)

__global__ __launch_bounds__(256, 2) void gemm_main(
    const __half* __restrict__ z2, const __half* __restrict__ wkv2,
    const __half* __restrict__ x2, const __half* __restrict__ wq2,
    __half* __restrict__ Ckv, __half* __restrict__ Cq,
    const float* __restrict__ zrot, const float* __restrict__ xrot, int bx0)
{
    extern __shared__ __align__(1024) char smem[];
    const int bx = blockIdx.x + bx0;
    const int isKv = (bx < 8);
    const __half* A2 = isKv ? z2 : x2;
    const __half* B2 = isKv ? wkv2 : wq2;
    const int n0 = (isKv ? bx : bx - 8) * 128;
    const int m0 = blockIdx.y * 128;
    const int tid = threadIdx.x, lane = tid & 31, wid = tid >> 5;
    const int wr = wid >> 2, wc = wid & 3;
    const u32 sb = smem_u32(smem);

    const int K2 = 256, total = 8;
    const int lrow = tid >> 1;
    const int lcg = (tid & 1) * 2;

    float acc[4][4][4];
    #pragma unroll
    for (int i = 0; i < 4; i++)
        #pragma unroll
        for (int j = 0; j < 4; j++)
            #pragma unroll
            for (int r = 0; r < 4; r++) acc[i][j][r] = 0.f;

    auto issue = [&](int it) {
        const int stage = it & (NSTAGE - 1);
        const int kk = it * 32;
        const __half* as = A2 + (size_t)(m0 + lrow) * K2 + kk + lcg * 8;
        const __half* bs = B2 + (size_t)(n0 + lrow) * K2 + kk + lcg * 8;
        const u32 da = sb + stage * STAGEB + lrow * ROWB + lcg * 16;
        cpa16(da, as);              cpa16(da + 16, as + 8);
        cpa16(da + TILEB, bs);      cpa16(da + TILEB + 16, bs + 8);
        CP_COMMIT();
    };

    auto compute = [&](int stage) {
        const u32 ab = sb + stage * STAGEB;
        const u32 bb = ab + TILEB;
        #pragma unroll
        for (int kb = 0; kb < 2; kb++) {
            u32 a[4][4], b[2][4];
            #pragma unroll
            for (int mf = 0; mf < 4; mf++) {
                u32 addr = ab + (u32)(wr * 64 + mf * 16 + (lane & 15)) * ROWB
                              + kb * 32 + (lane >> 4) * 16;
                ldsm4(a[mf], addr);
            }
            #pragma unroll
            for (int nfp = 0; nfp < 2; nfp++) {
                u32 addr = bb + (u32)(wc * 32 + nfp * 16 + ((lane >> 4) << 3) + (lane & 7)) * ROWB
                              + kb * 32 + ((lane >> 3) & 1) * 16;
                ldsm4(b[nfp], addr);
            }
            #pragma unroll
            for (int mf = 0; mf < 4; mf++)
                #pragma unroll
                for (int nf = 0; nf < 4; nf++)
                    mma16816h(acc[mf][nf], a[mf], &b[nf >> 1][(nf & 1) * 2]);
        }
    };

    issue(0); issue(1); issue(2);
    for (int i = 0; i < total; i++) {
        if (i < total - 2)       CP_WAIT(2);
        else if (i == total - 2) CP_WAIT(1);
        else                     CP_WAIT(0);
        __syncthreads();
        compute(i & (NSTAGE - 1));
        if (i + 3 < total) issue(i + 3);
    }

    if (isKv) {
        __syncthreads();                        // mainloop smem dead; reuse
        float* red  = (float*)smem;             // 8 KB reduction exchange
        float* tblf = (float*)(smem + 8192);    // rot table, stride TSTRIDE floats
        const int isK = (bx < 4);

        float s8[8], q8[8], mean[8], inv[8];
        #pragma unroll
        for (int mf = 0; mf < 4; mf++)
            #pragma unroll
            for (int rb = 0; rb < 2; rb++) {
                const int ri = mf * 2 + rb;
                float s = 0.f, q = 0.f;
                #pragma unroll
                for (int nf = 0; nf < 4; nf++)
                    #pragma unroll
                    for (int cb = 0; cb < 2; cb++) {
                        float a = acc[mf][nf][rb * 2 + cb];
                        s += a; q += a * a;
                    }
                s += __shfl_xor_sync(0xffffffffu, s, 1); q += __shfl_xor_sync(0xffffffffu, q, 1);
                s += __shfl_xor_sync(0xffffffffu, s, 2); q += __shfl_xor_sync(0xffffffffu, q, 2);
                s8[ri] = s; q8[ri] = q;
            }
        if ((lane & 3) == 0) {
            #pragma unroll
            for (int ri = 0; ri < 8; ri++) {
                const int idx = (((wr * 4 + wc) * 8) + ri) * 8 + (lane >> 2);
                red[idx * 2] = s8[ri]; red[idx * 2 + 1] = q8[ri];
            }
        }
        if (isK) {
            // stage rot table rows [m0, m0+128) (coalesced), overlapped with reduction
            #pragma unroll
            for (int it = 0; it < 8; it++) {
                const int idx = it * 256 + tid;
                const int row = idx >> 4, c4 = idx & 15;
                const float4 v = *(const float4*)(zrot + (size_t)(m0 + row) * 64 + c4 * 4);
                *(float4*)(tblf + row * TSTRIDE + c4 * 4) = v;
            }
        }
        __syncthreads();
        #pragma unroll
        for (int ri = 0; ri < 8; ri++) {
            const int idx = (((wr * 4 + (wc ^ 1)) * 8) + ri) * 8 + (lane >> 2);
            const float ts = s8[ri] + red[idx * 2];
            const float tq = q8[ri] + red[idx * 2 + 1];
            const float mu = ts * (1.f / 64.f);
            mean[ri] = mu;
            inv[ri] = rsqrtf(fmaxf(tq * (1.f / 64.f) - mu * mu, 0.f) + 1e-5f);
        }

        const int g = (isK ? bx : bx - 4) * 2 + (wc >> 1);
        const int half = wc & 1;
        const int lq = lane & 3;
        __half* base0 = Ckv + (isK ? 0 : PL);
        const float2* tbl2 = (const float2*)tblf;
        #pragma unroll
        for (int mf = 0; mf < 4; mf++)
            #pragma unroll
            for (int rb = 0; rb < 2; rb++) {
                const int ri = mf * 2 + rb;
                const int mr = wr * 64 + mf * 16 + (lane >> 2) + rb * 8;
                const int m = m0 + mr;
                const int bb = m >> 12, tt = m & 4095;
                const size_t rowoff = ((size_t)(bb * 8 + g) * 4096 + tt) * 64;
                const float mu = mean[ri], iv = inv[ri];
                if (isK) {
                    const float2* t2 = tbl2 + (size_t)mr * (TSTRIDE / 2) + half * 16;
                    #pragma unroll
                    for (int nf2 = 0; nf2 < 2; nf2++) {
                        float o[4];
                        #pragma unroll
                        for (int cb = 0; cb < 2; cb++) {
                            const int j = nf2 * 8 + lq * 2 + cb;
                            const float2 cs = t2[j];
                            const float vlo = (acc[mf][nf2][rb * 2 + cb]     - mu) * iv;
                            const float vhi = (acc[mf][nf2 + 2][rb * 2 + cb] - mu) * iv;
                            o[cb]     = vlo * cs.x - vhi * cs.y;
                            o[2 + cb] = vhi * cs.x + vlo * cs.y;
                        }
                        const int cg = half * 32 + nf2 * 8 + lq * 2;
                        *(__half2*)&base0[rowoff + cg] =
                            __half2{__float2half_rn(o[0]), __float2half_rn(o[1])};
                        *(__half2*)&base0[rowoff + cg + 16] =
                            __half2{__float2half_rn(o[2]), __float2half_rn(o[3])};
                    }
                } else {
                    #pragma unroll
                    for (int nf = 0; nf < 4; nf++) {
                        const int cg = half * 32 + nf * 8 + lq * 2;
                        const float a0 = (acc[mf][nf][rb * 2]     - mu) * iv;
                        const float a1 = (acc[mf][nf][rb * 2 + 1] - mu) * iv;
                        *(__half2*)&base0[rowoff + cg] =
                            __half2{__float2half_rn(a0), __float2half_rn(a1)};
                    }
                }
            }
    } else {
        // q branch: staged rot table + fp16 store -> Cq [M, 512]
        __syncthreads();
        float* tblf = (float*)smem;
        #pragma unroll
        for (int it = 0; it < 8; it++) {
            const int idx = it * 256 + tid;
            const int row = idx >> 4, c4 = idx & 15;
            const float4 v = *(const float4*)(xrot + (size_t)(m0 + row) * 64 + c4 * 4);
            *(float4*)(tblf + row * TSTRIDE + c4 * 4) = v;
        }
        __syncthreads();
        const float2* tbl2 = (const float2*)tblf;
        const int half = wc & 1;
        const int lq = lane & 3;
        #pragma unroll
        for (int mf = 0; mf < 4; mf++) {
            #pragma unroll
            for (int rb = 0; rb < 2; rb++) {
                const int mr = wr * 64 + mf * 16 + (lane >> 2) + rb * 8;
                const int r = m0 + mr;
                const size_t rowb = (size_t)r * 512;
                const float2* t2 = tbl2 + (size_t)mr * (TSTRIDE / 2) + half * 16;
                #pragma unroll
                for (int nf2 = 0; nf2 < 2; nf2++) {
                    float o[4];
                    #pragma unroll
                    for (int cb = 0; cb < 2; cb++) {
                        const int j = nf2 * 8 + lq * 2 + cb;
                        const float2 cs = t2[j];
                        const int idx = rb * 2 + cb;
                        const float vlo = acc[mf][nf2][idx];
                        const float vhi = acc[mf][nf2 + 2][idx];
                        o[cb]     = vlo * cs.x - vhi * cs.y;
                        o[2 + cb] = vhi * cs.x + vlo * cs.y;
                    }
                    const int cg = n0 + wc * 32 + nf2 * 8 + lq * 2;
                    *(__half2*)&Cq[rowb + cg] =
                        __half2{__float2half_rn(o[0]), __float2half_rn(o[1])};
                    *(__half2*)&Cq[rowb + cg + 16] =
                        __half2{__float2half_rn(o[2]), __float2half_rn(o[3])};
                }
            }
        }
    }
}

// ---------------- epilogue GEMM: out[b] = q2[b] @ W2s[b]^T + bout ----------------------
__global__ __launch_bounds__(256, 2) void gemm_epi(
    const __half* __restrict__ A2, const __half* __restrict__ B2,
    float* __restrict__ C, const float* __restrict__ bias)
{
    extern __shared__ __align__(1024) char smem[];
    A2 += (size_t)blockIdx.z * ((long)NTOKS * 512);
    B2 += (size_t)blockIdx.z * ((long)256 * 512);
    C  += (size_t)blockIdx.z * ((long)NTOKS * 256);
    const int m0 = blockIdx.y * 128, n0 = blockIdx.x * 128;
    const int tid = threadIdx.x, lane = tid & 31, wid = tid >> 5;
    const int wr = wid >> 2, wc = wid & 3;
    const u32 sb = smem_u32(smem);

    const int K2 = 512, total = 16;
    const int lrow = tid >> 1;
    const int lcg = (tid & 1) * 2;

    float acc[4][4][4];
    #pragma unroll
    for (int i = 0; i < 4; i++)
        #pragma unroll
        for (int j = 0; j < 4; j++)
            #pragma unroll
            for (int r = 0; r < 4; r++) acc[i][j][r] = 0.f;

    auto issue = [&](int it) {
        const int stage = it & (NSTAGE - 1);
        const int kk = it * 32;
        const __half* as = A2 + (size_t)(m0 + lrow) * K2 + kk + lcg * 8;
        const __half* bs = B2 + (size_t)(n0 + lrow) * K2 + kk + lcg * 8;
        const u32 da = sb + stage * STAGEB + lrow * ROWB + lcg * 16;
        cpa16(da, as);              cpa16(da + 16, as + 8);
        cpa16(da + TILEB, bs);      cpa16(da + TILEB + 16, bs + 8);
        CP_COMMIT();
    };

    auto compute = [&](int stage) {
        const u32 ab = sb + stage * STAGEB;
        const u32 bb = ab + TILEB;
        #pragma unroll
        for (int kb = 0; kb < 2; kb++) {
            u32 a[4][4], b[2][4];
            #pragma unroll
            for (int mf = 0; mf < 4; mf++) {
                u32 addr = ab + (u32)(wr * 64 + mf * 16 + (lane & 15)) * ROWB
                              + kb * 32 + (lane >> 4) * 16;
                ldsm4(a[mf], addr);
            }
            #pragma unroll
            for (int nfp = 0; nfp < 2; nfp++) {
                u32 addr = bb + (u32)(wc * 32 + nfp * 16 + ((lane >> 4) << 3) + (lane & 7)) * ROWB
                              + kb * 32 + ((lane >> 3) & 1) * 16;
                ldsm4(b[nfp], addr);
            }
            #pragma unroll
            for (int mf = 0; mf < 4; mf++)
                #pragma unroll
                for (int nf = 0; nf < 4; nf++)
                    mma16816h(acc[mf][nf], a[mf], &b[nf >> 1][(nf & 1) * 2]);
        }
    };

    issue(0); issue(1); issue(2);
    for (int i = 0; i < total; i++) {
        if (i < total - 2)       CP_WAIT(2);
        else if (i == total - 2) CP_WAIT(1);
        else                     CP_WAIT(0);
        __syncthreads();
        compute(i & (NSTAGE - 1));
        if (i + 3 < total) issue(i + 3);
    }

    const int rbase = m0 + wr * 64 + (lane >> 2);
    const int cbase = n0 + wc * 32 + (lane & 3) * 2;
    #pragma unroll
    for (int nf = 0; nf < 4; nf++) {
        const int c = cbase + nf * 8;
        const float bx = bias[c], by = bias[c + 1];
        #pragma unroll
        for (int mf = 0; mf < 4; mf++) {
            const int r = rbase + mf * 16;
            *(float2*)&C[(size_t)r * 256 + c] =
                make_float2(acc[mf][nf][0] + bx, acc[mf][nf][1] + by);
            *(float2*)&C[(size_t)(r + 8) * 256 + c] =
                make_float2(acc[mf][nf][2] + bx, acc[mf][nf][3] + by);
        }
    }
}

// ---------------- dots: pure streaming fp16 Gram MMA ----------------
#define DROWB 144
#define DTILE (64 * DROWB)
#define DSTG2 (2 * DTILE)
#define DSM_BYTES (2 * DSTG2)

__global__ __launch_bounds__(256, 2) void dots_pure(const __half* __restrict__ kvs,
                                                    float* __restrict__ part) {
    extern __shared__ __align__(1024) char dsm[];
    const u32 sb = smem_u32(dsm);

    const int split = blockIdx.x;
    const int bh = blockIdx.y;
    const int tid = threadIdx.x;
    const int w = tid >> 5, lane = tid & 31;
    const int wr = w >> 1, wc = w & 1;

    float acc[4][4];
    #pragma unroll
    for (int i = 0; i < 4; i++)
        #pragma unroll
        for (int j = 0; j < 4; j++) acc[i][j] = 0.f;

    auto issue = [&](int c) {
        const int t0 = split * 256 + c * 64;
        const u32 sbase = sb + (c & 1) * DSTG2;
        #pragma unroll
        for (int i = 0; i < 4; i++) {
            const int idx = i * 256 + tid;
            const int plane = idx >> 9;
            const int r = (idx >> 3) & 63;
            const int seg = idx & 7;
            const __half* src = kvs + (size_t)plane * PL
                + ((size_t)bh * 4096 + t0 + r) * 64 + seg * 8;
            cpa16(sbase + plane * DTILE + r * DROWB + seg * 16, src);
        }
        CP_COMMIT();
    };

    issue(0);
    for (int c = 0; c < 4; c++) {
        if (c < 3) { issue(c + 1); CP_WAIT(1); } else { CP_WAIT(0); }
        __syncthreads();
        const u32 khb = sb + (c & 1) * DSTG2;
        const u32 vhb = khb + DTILE;
        #pragma unroll
        for (int kt = 0; kt < 4; kt++) {
            const u32 arow = (u32)(kt * 16 + (lane & 7) + ((lane >> 4) << 3));
            const u32 acol = (u32)(wr * 16 + ((lane >> 3) & 1) * 8);
            u32 ah[4];
            ldsm4t(ah, khb + arow * DROWB + acol * 2);
            const u32 brow = (u32)(kt * 16 + (lane & 7) + ((lane >> 3) & 1) * 8);
            const u32 bcol = (u32)(wc * 32 + ((lane >> 4) << 3));
            const u32 boff = brow * DROWB + bcol * 2;
            u32 bh0[4], bh1[4];
            ldsm4t(bh0, vhb + boff);
            ldsm4t(bh1, vhb + boff + 32);
            mma16816h(acc[0], ah, &bh0[0]);
            mma16816h(acc[1], ah, &bh0[2]);
            mma16816h(acc[2], ah, &bh1[0]);
            mma16816h(acc[3], ah, &bh1[2]);
        }
        __syncthreads();
    }

    float* dst = part + ((size_t)bh * NSPLIT + split) * 4096;
    const int dr = wr * 16 + (lane >> 2);
    const int ec = wc * 32 + (lane & 3) * 2;
    #pragma unroll
    for (int nf = 0; nf < 4; nf++) {
        *(float2*)&dst[(size_t)dr * 64 + ec + nf * 8]       = make_float2(acc[nf][0], acc[nf][1]);
        *(float2*)&dst[(size_t)(dr + 8) * 64 + ec + nf * 8] = make_float2(acc[nf][2], acc[nf][3]);
    }
}

// ---------------- w2k: W2s = fp16( ((sum dots)/n2 @ Wout)^T ), 4-wide LDG batching -----
__global__ __launch_bounds__(256) void w2k(const float* __restrict__ part, const float* __restrict__ Wout,
                                           __half* __restrict__ W2s) {
    const int bh = blockIdx.x, dg = blockIdx.y;
    const int b = bh >> 3, h = bh & 7;
    __shared__ float ds[512];                      // [8 d][64 e]
    const int tid = threadIdx.x;
    if (tid < 128) {
        float4 s = make_float4(0.f, 0.f, 0.f, 0.f);
        const float4* base = (const float4*)(part + (size_t)bh * NSPLIT * 4096 + dg * 512) + tid;
        #pragma unroll
        for (int sp = 0; sp < NSPLIT; sp++) {
            const float4 v = base[sp * 1024];
            s.x += v.x; s.y += v.y; s.z += v.z; s.w += v.w;
        }
        *(float4*)&ds[tid * 4] = make_float4(s.x * (1.f / 4096.f), s.y * (1.f / 4096.f),
                                             s.z * (1.f / 4096.f), s.w * (1.f / 4096.f));
    }
    __syncthreads();

    const int p = tid & 127, dq = tid >> 7;
    u64 acc[4];
    #pragma unroll
    for (int d = 0; d < 4; d++) acc[d] = 0ull;
    const float* wbase = Wout + (size_t)(h * 64) * 256 + 2 * p;
    #pragma unroll 2
    for (int e = 0; e < 64; e += 4) {
        const u64 w0 = *(const u64*)(wbase + (size_t)(e + 0) * 256);
        const u64 w1 = *(const u64*)(wbase + (size_t)(e + 1) * 256);
        const u64 w2 = *(const u64*)(wbase + (size_t)(e + 2) * 256);
        const u64 w3 = *(const u64*)(wbase + (size_t)(e + 3) * 256);
        const float* dsr = &ds[(dq * 4) * 64 + e];
        #pragma unroll
        for (int d = 0; d < 4; d++) {
            const float* r = dsr + d * 64;
            acc[d] = ffma2(pack2(r[0], r[0]), w0, acc[d]);
            acc[d] = ffma2(pack2(r[1], r[1]), w1, acc[d]);
            acc[d] = ffma2(pack2(r[2], r[2]), w2, acc[d]);
            acc[d] = ffma2(pack2(r[3], r[3]), w3, acc[d]);
        }
    }
    #pragma unroll
    for (int d = 0; d < 4; d++) {
        float o0, o1; unpack2(acc[d], o0, o1);
        const int dgg = h * 64 + dg * 8 + dq * 4 + d;
        size_t r0 = ((size_t)b * 256 + 2 * p) * 512;
        W2s[r0 + dgg]       = __float2half_rn(o0);
        W2s[r0 + 512 + dgg] = __float2half_rn(o1);
    }
}

// ---------------- launch ----------------
extern "C" void kernel_launch(void* const* d_in, const int* in_sizes, int n_in,
                              void* d_out, int out_size) {
    const float* x     = (const float*)d_in[0];
    const float* z     = (const float*)d_in[1];
    const float* x_pos = (const float*)d_in[2];
    const float* z_pos = (const float*)d_in[3];
    const float* Wq    = (const float*)d_in[4];
    const float* Wkv   = (const float*)d_in[5];
    const float* Wout  = (const float*)d_in[6];
    const float* bout  = (const float*)d_in[7];
    float* out = (float*)d_out;

    float *dotp, *zrot, *xrot;
    __half *kvs, *z2, *x2, *wkv2, *wq2, *q2, *w2s;
    cudaGetSymbolAddress((void**)&kvs,  g_kvs);
    cudaGetSymbolAddress((void**)&dotp, g_dotp);
    cudaGetSymbolAddress((void**)&z2,   g_z2);
    cudaGetSymbolAddress((void**)&x2,   g_x2);
    cudaGetSymbolAddress((void**)&wkv2, g_wkv2);
    cudaGetSymbolAddress((void**)&wq2,  g_wq2);
    cudaGetSymbolAddress((void**)&q2,   g_q2);
    cudaGetSymbolAddress((void**)&w2s,  g_w2s);
    cudaGetSymbolAddress((void**)&zrot, g_zrot);
    cudaGetSymbolAddress((void**)&xrot, g_xrot);

    // lazy one-time host resources (no device memory involved)
    static cudaStream_t s2 = nullptr;
    static cudaEvent_t evRoot = nullptr, evKV = nullptr, evQ = nullptr;
    if (!s2) {
        cudaStreamCreateWithFlags(&s2, cudaStreamNonBlocking);
        cudaEventCreateWithFlags(&evRoot, cudaEventDisableTiming);
        cudaEventCreateWithFlags(&evKV, cudaEventDisableTiming);
        cudaEventCreateWithFlags(&evQ, cudaEventDisableTiming);
        cudaFuncSetAttribute(gemm_main, cudaFuncAttributeMaxDynamicSharedMemorySize, GSMEM);
        cudaFuncSetAttribute(gemm_epi,  cudaFuncAttributeMaxDynamicSharedMemorySize, GSMEM);
        cudaFuncSetAttribute(dots_pure, cudaFuncAttributeMaxDynamicSharedMemorySize, DSM_BYTES);
    }

    // fork side stream; both prep halves run concurrently (memory-bound, share BW)
    cudaEventRecord(evRoot, 0);
    cudaStreamWaitEvent(s2, evRoot, 0);

    prep_part<<<11264, 256>>>(z, Wkv, z2, wkv2, 1024, z_pos, zrot);      // main: z + Wkv + zrot
    prep_part<<<10752, 256, 0, s2>>>(x, Wq, x2, wq2, 512, x_pos, xrot);  // side: x + Wq + xrot

    // kv GEMM on main stream (needs z2/wkv2/zrot)
    gemm_main<<<dim3(8, 256), 256, GSMEM>>>(z2, wkv2, x2, wq2, kvs, q2, zrot, xrot, 0);
    cudaEventRecord(evKV, 0);

    // q GEMM on side stream AFTER kv completes -> overlaps dots+w2k (different pipes)
    cudaStreamWaitEvent(s2, evKV, 0);
    gemm_main<<<dim3(4, 256), 256, GSMEM, s2>>>(z2, wkv2, x2, wq2, kvs, q2, zrot, xrot, 8);
    cudaEventRecord(evQ, s2);

    // dots + w2k on main stream (DRAM / latency bound; co-run with q GEMM)
    dots_pure<<<dim3(NSPLIT, 64), 256, DSM_BYTES>>>(kvs, dotp);
    w2k<<<dim3(64, 8), 256>>>(dotp, Wout, w2s);

    // join: epilogue needs q2 (side) + w2s (main)
    cudaStreamWaitEvent(0, evQ, 0);
    gemm_epi<<<dim3(2, 32, BATCH), 256, GSMEM>>>(q2, w2s, out, bout);
}

// round 17
// speedup vs baseline: 1.0733x; 1.0095x over previous
#include <cuda_runtime.h>
#include <cuda_bf16.h>
#include <cuda_fp16.h>
#include <math.h>
#include <cstdint>

typedef unsigned long long u64;
typedef unsigned int u32;

#define HEADS 8
#define NDIM  256
#define INNER 512
#define NTOKS 4096
#define BATCH 8
#define MTOT  (BATCH * NTOKS)   // 32768
#define NSPLIT 16
#define PL ((size_t)64 * 4096 * 64)   // one fp16 plane: [b*8+h][t][64]

// ---------------- scratch (device globals: allocation-guard safe) ----------------
__device__ __half g_kvs [(size_t)2 * PL];            // plane 0: k~, plane 1: v~ (fp16)
__device__ float g_dotp[(size_t)64 * NSPLIT * 64 * 64];
__device__ __half g_z2  [(size_t)MTOT * 256];        // z fp16
__device__ __half g_x2  [(size_t)MTOT * 256];
__device__ __half g_wkv2[(size_t)1024 * 256];        // Wkv^T fp16
__device__ __half g_wq2 [(size_t)512 * 256];         // Wq^T fp16
__device__ __half g_q2  [(size_t)MTOT * 512];        // q rot fp16 [M, INNER]
__device__ __half g_w2s [(size_t)BATCH * 256 * 512]; // W2^T fp16
__device__ float g_zrot[(size_t)MTOT * 64];          // rot table z
__device__ float g_xrot[(size_t)MTOT * 64];          // rot table x

// ---------------- MMA / async helpers ----------------
__device__ __forceinline__ u32 smem_u32(const void* p) {
    u32 a; asm("{ .reg .u64 t; cvta.to.shared.u64 t, %1; cvt.u32.u64 %0, t; }" : "=r"(a) : "l"(p));
    return a;
}
__device__ __forceinline__ void cpa16(u32 dst, const void* src) {
    asm volatile("cp.async.cg.shared.global [%0], [%1], 16;" :: "r"(dst), "l"(src));
}
#define CP_COMMIT() asm volatile("cp.async.commit_group;" ::: "memory")
#define CP_WAIT(n)  asm volatile("cp.async.wait_group %0;" :: "n"(n) : "memory")

__device__ __forceinline__ void ldsm4(u32* r, u32 a) {
    asm volatile("ldmatrix.sync.aligned.m8n8.x4.shared.b16 {%0,%1,%2,%3}, [%4];"
        : "=r"(r[0]), "=r"(r[1]), "=r"(r[2]), "=r"(r[3]) : "r"(a));
}
__device__ __forceinline__ void ldsm4t(u32* r, u32 a) {
    asm volatile("ldmatrix.sync.aligned.m8n8.x4.trans.shared.b16 {%0,%1,%2,%3}, [%4];"
        : "=r"(r[0]), "=r"(r[1]), "=r"(r[2]), "=r"(r[3]) : "r"(a));
}
__device__ __forceinline__ void mma16816h(float* c, const u32* a, const u32* b) {
    asm volatile("mma.sync.aligned.m16n8k16.row.col.f32.f16.f16.f32 "
        "{%0,%1,%2,%3}, {%4,%5,%6,%7}, {%8,%9}, {%0,%1,%2,%3};"
        : "+f"(c[0]), "+f"(c[1]), "+f"(c[2]), "+f"(c[3])
        : "r"(a[0]), "r"(a[1]), "r"(a[2]), "r"(a[3]), "r"(b[0]), "r"(b[1]));
}

// ---------------- f32x2 helpers ----------------
__device__ __forceinline__ u64 pack2(float x, float y) {
    u64 r; asm("mov.b64 %0, {%1,%2};" : "=l"(r) : "f"(x), "f"(y)); return r;
}
__device__ __forceinline__ u64 ffma2(u64 a, u64 b, u64 c) {
    u64 d; asm("fma.rn.f32x2 %0, %1, %2, %3;" : "=l"(d) : "l"(a), "l"(b), "l"(c)); return d;
}
__device__ __forceinline__ void unpack2(u64 v, float& x, float& y) {
    asm("mov.b64 {%0,%1}, %2;" : "=f"(x), "=f"(y) : "l"(v));
}

// ---------------- prep: fp16 convert data + coalesced weight^T + rotary table ----------
// blocks: [0,8192) data rows; [8192, 8192+Nw/32*8) weight tiles (32x32); rest: rot table.
__global__ void prep_part(const float* __restrict__ in, const float* __restrict__ W,
                          __half* __restrict__ out, __half* __restrict__ wout, int Nw,
                          const float* __restrict__ pos, float* __restrict__ rot) {
    const int bid = blockIdx.x, tid = threadIdx.x;
    const int nwt = (Nw >> 5) * 8;   // weight tile blocks (each block: 8 tiles of 32x32)
    if (bid < 8192) {
        size_t idx = (size_t)bid * 256 + tid;     // one float4
        float4 v = ((const float4*)in)[idx];
        __half2 p0 = __half2{__float2half_rn(v.x), __float2half_rn(v.y)};
        __half2 p1 = __half2{__float2half_rn(v.z), __float2half_rn(v.w)};
        __half2* dst = (__half2*)(out + idx * 4);
        dst[0] = p0; dst[1] = p1;
    } else if (bid < 8192 + nwt) {
        // coalesced transpose of a 32x32 tile of W [256, Nw] -> wout [Nw, 256]
        __shared__ float tile[32][33];
        const int t = bid - 8192;                 // tile index: (krow, ncol) grid 8 x Nw/32
        const int kt = t >> (Nw == 1024 ? 5 : 4); // 8 rows of tiles
        const int nt = t & ((Nw >> 5) - 1);
        const int r = tid >> 3, c4 = (tid & 7) * 4;  // 32 rows x 8 float4
        const float4 v = *(const float4*)(W + (size_t)(kt * 32 + r) * Nw + nt * 32 + c4);
        tile[r][c4] = v.x; tile[r][c4 + 1] = v.y; tile[r][c4 + 2] = v.z; tile[r][c4 + 3] = v.w;
        __syncthreads();
        const int nr = tid >> 3, kc = (tid & 7) * 4;  // write 32 n-rows x 8 k-groups
        __half2 h0 = __half2{__float2half_rn(tile[kc][nr]),     __float2half_rn(tile[kc + 1][nr])};
        __half2 h1 = __half2{__float2half_rn(tile[kc + 2][nr]), __float2half_rn(tile[kc + 3][nr])};
        __half2* dst = (__half2*)(wout + (size_t)(nt * 32 + nr) * 256 + kt * 32 + kc);
        dst[0] = h0; dst[1] = h1;
    } else {
        const int bid_r = bid - 8192 - nwt;
        const int token = bid_r * 16 + (tid >> 4);
        const int j = tid & 15;
        const float px = pos[(size_t)token * 2]     * 64.f;
        const float py = pos[(size_t)token * 2 + 1] * 64.f;
        const float invf = exp2f(-(float)j * (13.287712379549449f / 16.f));
        float sx, cx, sy, cy;
        sincosf(px * invf, &sx, &cx);
        sincosf(py * invf, &sy, &cy);
        float2* r2 = (float2*)(rot + (size_t)token * 64);
        r2[j]      = make_float2(cx, sx);
        r2[16 + j] = make_float2(cy, sy);
    }
}

// ---------------- shared GEMM mainloop pieces ----------------
#define ROWB 80
#define TILEB (128 * ROWB)
#define STAGEB (2 * TILEB)
#define NSTAGE 4
#define GSMEM (NSTAGE * STAGEB)
#define TSTRIDE 72

struct MLoop {
    u32 sb; int tid, lane, wr, wc, lrow, lcg;
    __device__ __forceinline__ void init(u32 sb_, int tid_) {
        sb = sb_; tid = tid_; lane = tid & 31;
        const int wid = tid >> 5;
        wr = wid >> 2; wc = wid & 3;
        lrow = tid >> 1; lcg = (tid & 1) * 2;
    }
    __device__ __forceinline__ void issue(const __half* A, const __half* B, int K2, int it) {
        const int stage = it & (NSTAGE - 1);
        const int kk = it * 32;
        const __half* as = A + (size_t)lrow * K2 + kk + lcg * 8;
        const __half* bs = B + (size_t)lrow * K2 + kk + lcg * 8;
        const u32 da = sb + stage * STAGEB + lrow * ROWB + lcg * 16;
        cpa16(da, as);              cpa16(da + 16, as + 8);
        cpa16(da + TILEB, bs);      cpa16(da + TILEB + 16, bs + 8);
        CP_COMMIT();
    }
    __device__ __forceinline__ void compute(float acc[4][4][4], int stage) {
        const u32 ab = sb + stage * STAGEB;
        const u32 bb = ab + TILEB;
        #pragma unroll
        for (int kb = 0; kb < 2; kb++) {
            u32 a[4][4], b[2][4];
            #pragma unroll
            for (int mf = 0; mf < 4; mf++) {
                u32 addr = ab + (u32)(wr * 64 + mf * 16 + (lane & 15)) * ROWB
                              + kb * 32 + (lane >> 4) * 16;
                ldsm4(a[mf], addr);
            }
            #pragma unroll
            for (int nfp = 0; nfp < 2; nfp++) {
                u32 addr = bb + (u32)(wc * 32 + nfp * 16 + ((lane >> 4) << 3) + (lane & 7)) * ROWB
                              + kb * 32 + ((lane >> 3) & 1) * 16;
                ldsm4(b[nfp], addr);
            }
            #pragma unroll
            for (int mf = 0; mf < 4; mf++)
                #pragma unroll
                for (int nf = 0; nf < 4; nf++)
                    mma16816h(acc[mf][nf], a[mf], &b[nf >> 1][(nf & 1) * 2]);
        }
    }
    __device__ __forceinline__ void run(float acc[4][4][4], const __half* A, const __half* B,
                                        int K2, int total) {
        issue(A, B, K2, 0); issue(A, B, K2, 1); issue(A, B, K2, 2);
        for (int i = 0; i < total; i++) {
            if (i < total - 2)       CP_WAIT(2);
            else if (i == total - 2) CP_WAIT(1);
            else                     CP_WAIT(0);
            __syncthreads();
            compute(acc, i & (NSTAGE - 1));
            if (i + 3 < total) issue(A, B, K2, i + 3);
        }
    }
};

// ---------------- kv GEMM: norm + rotary(k) -> fp16 planes ----------------
__global__ __launch_bounds__(256, 2) void gemm_kv(
    const __half* __restrict__ z2, const __half* __restrict__ wkv2,
    __half* __restrict__ Ckv, const float* __restrict__ zrot)
{
    extern __shared__ __align__(1024) char smem[];
    const int bx = blockIdx.x;
    const int n0 = bx * 128;
    const int m0 = blockIdx.y * 128;
    MLoop ml; ml.init(smem_u32(smem), threadIdx.x);
    const int tid = ml.tid, lane = ml.lane, wr = ml.wr, wc = ml.wc;

    float acc[4][4][4];
    #pragma unroll
    for (int i = 0; i < 4; i++)
        #pragma unroll
        for (int j = 0; j < 4; j++)
            #pragma unroll
            for (int r = 0; r < 4; r++) acc[i][j][r] = 0.f;

    ml.run(acc, z2 + (size_t)m0 * 256, wkv2 + (size_t)n0 * 256, 256, 8);

    __syncthreads();
    float* red  = (float*)smem;
    float* tblf = (float*)(smem + 8192);
    const int isK = (bx < 4);

    float s8[8], q8[8], mean[8], inv[8];
    #pragma unroll
    for (int mf = 0; mf < 4; mf++)
        #pragma unroll
        for (int rb = 0; rb < 2; rb++) {
            const int ri = mf * 2 + rb;
            float s = 0.f, q = 0.f;
            #pragma unroll
            for (int nf = 0; nf < 4; nf++)
                #pragma unroll
                for (int cb = 0; cb < 2; cb++) {
                    float a = acc[mf][nf][rb * 2 + cb];
                    s += a; q += a * a;
                }
            s += __shfl_xor_sync(0xffffffffu, s, 1); q += __shfl_xor_sync(0xffffffffu, q, 1);
            s += __shfl_xor_sync(0xffffffffu, s, 2); q += __shfl_xor_sync(0xffffffffu, q, 2);
            s8[ri] = s; q8[ri] = q;
        }
    if ((lane & 3) == 0) {
        #pragma unroll
        for (int ri = 0; ri < 8; ri++) {
            const int idx = (((wr * 4 + wc) * 8) + ri) * 8 + (lane >> 2);
            red[idx * 2] = s8[ri]; red[idx * 2 + 1] = q8[ri];
        }
    }
    if (isK) {
        #pragma unroll
        for (int it = 0; it < 8; it++) {
            const int idx = it * 256 + tid;
            const int row = idx >> 4, c4 = idx & 15;
            const float4 v = *(const float4*)(zrot + (size_t)(m0 + row) * 64 + c4 * 4);
            *(float4*)(tblf + row * TSTRIDE + c4 * 4) = v;
        }
    }
    __syncthreads();
    #pragma unroll
    for (int ri = 0; ri < 8; ri++) {
        const int idx = (((wr * 4 + (wc ^ 1)) * 8) + ri) * 8 + (lane >> 2);
        const float ts = s8[ri] + red[idx * 2];
        const float tq = q8[ri] + red[idx * 2 + 1];
        const float mu = ts * (1.f / 64.f);
        mean[ri] = mu;
        inv[ri] = rsqrtf(fmaxf(tq * (1.f / 64.f) - mu * mu, 0.f) + 1e-5f);
    }

    const int g = (isK ? bx : bx - 4) * 2 + (wc >> 1);
    const int half = wc & 1;
    const int lq = lane & 3;
    __half* base0 = Ckv + (isK ? 0 : PL);
    const float2* tbl2 = (const float2*)tblf;
    #pragma unroll
    for (int mf = 0; mf < 4; mf++)
        #pragma unroll
        for (int rb = 0; rb < 2; rb++) {
            const int ri = mf * 2 + rb;
            const int mr = wr * 64 + mf * 16 + (lane >> 2) + rb * 8;
            const int m = m0 + mr;
            const int bb = m >> 12, tt = m & 4095;
            const size_t rowoff = ((size_t)(bb * 8 + g) * 4096 + tt) * 64;
            const float mu = mean[ri], iv = inv[ri];
            if (isK) {
                const float2* t2 = tbl2 + (size_t)mr * (TSTRIDE / 2) + half * 16;
                #pragma unroll
                for (int nf2 = 0; nf2 < 2; nf2++) {
                    float o[4];
                    #pragma unroll
                    for (int cb = 0; cb < 2; cb++) {
                        const int j = nf2 * 8 + lq * 2 + cb;
                        const float2 cs = t2[j];
                        const float vlo = (acc[mf][nf2][rb * 2 + cb]     - mu) * iv;
                        const float vhi = (acc[mf][nf2 + 2][rb * 2 + cb] - mu) * iv;
                        o[cb]     = vlo * cs.x - vhi * cs.y;
                        o[2 + cb] = vhi * cs.x + vlo * cs.y;
                    }
                    const int cg = half * 32 + nf2 * 8 + lq * 2;
                    *(__half2*)&base0[rowoff + cg] =
                        __half2{__float2half_rn(o[0]), __float2half_rn(o[1])};
                    *(__half2*)&base0[rowoff + cg + 16] =
                        __half2{__float2half_rn(o[2]), __float2half_rn(o[3])};
                }
            } else {
                #pragma unroll
                for (int nf = 0; nf < 4; nf++) {
                    const int cg = half * 32 + nf * 8 + lq * 2;
                    const float a0 = (acc[mf][nf][rb * 2]     - mu) * iv;
                    const float a1 = (acc[mf][nf][rb * 2 + 1] - mu) * iv;
                    *(__half2*)&base0[rowoff + cg] =
                        __half2{__float2half_rn(a0), __float2half_rn(a1)};
                }
            }
        }
}

// ---------------- q GEMM: rotary -> fp16 ----------------
__global__ __launch_bounds__(256, 2) void gemm_q(
    const __half* __restrict__ x2, const __half* __restrict__ wq2,
    __half* __restrict__ Cq, const float* __restrict__ xrot)
{
    extern __shared__ __align__(1024) char smem[];
    const int n0 = blockIdx.x * 128;
    const int m0 = blockIdx.y * 128;
    MLoop ml; ml.init(smem_u32(smem), threadIdx.x);
    const int tid = ml.tid, lane = ml.lane, wr = ml.wr, wc = ml.wc;

    float acc[4][4][4];
    #pragma unroll
    for (int i = 0; i < 4; i++)
        #pragma unroll
        for (int j = 0; j < 4; j++)
            #pragma unroll
            for (int r = 0; r < 4; r++) acc[i][j][r] = 0.f;

    ml.run(acc, x2 + (size_t)m0 * 256, wq2 + (size_t)n0 * 256, 256, 8);

    __syncthreads();
    float* tblf = (float*)smem;
    #pragma unroll
    for (int it = 0; it < 8; it++) {
        const int idx = it * 256 + tid;
        const int row = idx >> 4, c4 = idx & 15;
        const float4 v = *(const float4*)(xrot + (size_t)(m0 + row) * 64 + c4 * 4);
        *(float4*)(tblf + row * TSTRIDE + c4 * 4) = v;
    }
    __syncthreads();
    const float2* tbl2 = (const float2*)tblf;
    const int half = wc & 1;
    const int lq = lane & 3;
    #pragma unroll
    for (int mf = 0; mf < 4; mf++) {
        #pragma unroll
        for (int rb = 0; rb < 2; rb++) {
            const int mr = wr * 64 + mf * 16 + (lane >> 2) + rb * 8;
            const int r = m0 + mr;
            const size_t rowb = (size_t)r * 512;
            const float2* t2 = tbl2 + (size_t)mr * (TSTRIDE / 2) + half * 16;
            #pragma unroll
            for (int nf2 = 0; nf2 < 2; nf2++) {
                float o[4];
                #pragma unroll
                for (int cb = 0; cb < 2; cb++) {
                    const int j = nf2 * 8 + lq * 2 + cb;
                    const float2 cs = t2[j];
                    const int idx = rb * 2 + cb;
                    const float vlo = acc[mf][nf2][idx];
                    const float vhi = acc[mf][nf2 + 2][idx];
                    o[cb]     = vlo * cs.x - vhi * cs.y;
                    o[2 + cb] = vhi * cs.x + vlo * cs.y;
                }
                const int cg = n0 + wc * 32 + nf2 * 8 + lq * 2;
                *(__half2*)&Cq[rowb + cg] =
                    __half2{__float2half_rn(o[0]), __float2half_rn(o[1])};
                *(__half2*)&Cq[rowb + cg + 16] =
                    __half2{__float2half_rn(o[2]), __float2half_rn(o[3])};
            }
        }
    }
}

// ---------------- epilogue GEMM: out[b] = q2[b] @ W2s[b]^T + bout ----------------------
__global__ __launch_bounds__(256, 2) void gemm_epi(
    const __half* __restrict__ A2, const __half* __restrict__ B2,
    float* __restrict__ C, const float* __restrict__ bias)
{
    extern __shared__ __align__(1024) char smem[];
    A2 += (size_t)blockIdx.z * ((long)NTOKS * 512);
    B2 += (size_t)blockIdx.z * ((long)256 * 512);
    C  += (size_t)blockIdx.z * ((long)NTOKS * 256);
    const int m0 = blockIdx.y * 128, n0 = blockIdx.x * 128;
    MLoop ml; ml.init(smem_u32(smem), threadIdx.x);
    const int lane = ml.lane, wr = ml.wr, wc = ml.wc;

    float acc[4][4][4];
    #pragma unroll
    for (int i = 0; i < 4; i++)
        #pragma unroll
        for (int j = 0; j < 4; j++)
            #pragma unroll
            for (int r = 0; r < 4; r++) acc[i][j][r] = 0.f;

    ml.run(acc, A2 + (size_t)m0 * 512, B2 + (size_t)n0 * 512, 512, 16);

    const int rbase = m0 + wr * 64 + (lane >> 2);
    const int cbase = n0 + wc * 32 + (lane & 3) * 2;
    #pragma unroll
    for (int nf = 0; nf < 4; nf++) {
        const int c = cbase + nf * 8;
        const float bx = bias[c], by = bias[c + 1];
        #pragma unroll
        for (int mf = 0; mf < 4; mf++) {
            const int r = rbase + mf * 16;
            *(float2*)&C[(size_t)r * 256 + c] =
                make_float2(acc[mf][nf][0] + bx, acc[mf][nf][1] + by);
            *(float2*)&C[(size_t)(r + 8) * 256 + c] =
                make_float2(acc[mf][nf][2] + bx, acc[mf][nf][3] + by);
        }
    }
}

// ---------------- dots: pure streaming fp16 Gram MMA ----------------
#define DROWB 144
#define DTILE (64 * DROWB)
#define DSTG2 (2 * DTILE)
#define DSM_BYTES (2 * DSTG2)

__global__ __launch_bounds__(256, 2) void dots_pure(const __half* __restrict__ kvs,
                                                    float* __restrict__ part) {
    extern __shared__ __align__(1024) char dsm[];
    const u32 sb = smem_u32(dsm);

    const int split = blockIdx.x;
    const int bh = blockIdx.y;
    const int tid = threadIdx.x;
    const int w = tid >> 5, lane = tid & 31;
    const int wr = w >> 1, wc = w & 1;

    float acc[4][4];
    #pragma unroll
    for (int i = 0; i < 4; i++)
        #pragma unroll
        for (int j = 0; j < 4; j++) acc[i][j] = 0.f;

    auto issue = [&](int c) {
        const int t0 = split * 256 + c * 64;
        const u32 sbase = sb + (c & 1) * DSTG2;
        #pragma unroll
        for (int i = 0; i < 4; i++) {
            const int idx = i * 256 + tid;
            const int plane = idx >> 9;
            const int r = (idx >> 3) & 63;
            const int seg = idx & 7;
            const __half* src = kvs + (size_t)plane * PL
                + ((size_t)bh * 4096 + t0 + r) * 64 + seg * 8;
            cpa16(sbase + plane * DTILE + r * DROWB + seg * 16, src);
        }
        CP_COMMIT();
    };

    issue(0);
    for (int c = 0; c < 4; c++) {
        if (c < 3) { issue(c + 1); CP_WAIT(1); } else { CP_WAIT(0); }
        __syncthreads();
        const u32 khb = sb + (c & 1) * DSTG2;
        const u32 vhb = khb + DTILE;
        #pragma unroll
        for (int kt = 0; kt < 4; kt++) {
            const u32 arow = (u32)(kt * 16 + (lane & 7) + ((lane >> 4) << 3));
            const u32 acol = (u32)(wr * 16 + ((lane >> 3) & 1) * 8);
            u32 ah[4];
            ldsm4t(ah, khb + arow * DROWB + acol * 2);
            const u32 brow = (u32)(kt * 16 + (lane & 7) + ((lane >> 3) & 1) * 8);
            const u32 bcol = (u32)(wc * 32 + ((lane >> 4) << 3));
            const u32 boff = brow * DROWB + bcol * 2;
            u32 bh0[4], bh1[4];
            ldsm4t(bh0, vhb + boff);
            ldsm4t(bh1, vhb + boff + 32);
            mma16816h(acc[0], ah, &bh0[0]);
            mma16816h(acc[1], ah, &bh0[2]);
            mma16816h(acc[2], ah, &bh1[0]);
            mma16816h(acc[3], ah, &bh1[2]);
        }
        __syncthreads();
    }

    float* dst = part + ((size_t)bh * NSPLIT + split) * 4096;
    const int dr = wr * 16 + (lane >> 2);
    const int ec = wc * 32 + (lane & 3) * 2;
    #pragma unroll
    for (int nf = 0; nf < 4; nf++) {
        *(float2*)&dst[(size_t)dr * 64 + ec + nf * 8]       = make_float2(acc[nf][0], acc[nf][1]);
        *(float2*)&dst[(size_t)(dr + 8) * 64 + ec + nf * 8] = make_float2(acc[nf][2], acc[nf][3]);
    }
}

// ---------------- w2k: W2s = fp16( ((sum dots)/n2 @ Wout)^T ) ----------------
__global__ __launch_bounds__(256) void w2k(const float* __restrict__ part, const float* __restrict__ Wout,
                                           __half* __restrict__ W2s) {
    const int bh = blockIdx.x, dg = blockIdx.y;
    const int b = bh >> 3, h = bh & 7;
    __shared__ float ds[512];
    const int tid = threadIdx.x;
    if (tid < 128) {
        float4 s = make_float4(0.f, 0.f, 0.f, 0.f);
        const float4* base = (const float4*)(part + (size_t)bh * NSPLIT * 4096 + dg * 512) + tid;
        #pragma unroll
        for (int sp = 0; sp < NSPLIT; sp++) {
            const float4 v = base[sp * 1024];
            s.x += v.x; s.y += v.y; s.z += v.z; s.w += v.w;
        }
        *(float4*)&ds[tid * 4] = make_float4(s.x * (1.f / 4096.f), s.y * (1.f / 4096.f),
                                             s.z * (1.f / 4096.f), s.w * (1.f / 4096.f));
    }
    __syncthreads();

    const int p = tid & 127, dq = tid >> 7;
    u64 acc[4];
    #pragma unroll
    for (int d = 0; d < 4; d++) acc[d] = 0ull;
    const float* wbase = Wout + (size_t)(h * 64) * 256 + 2 * p;
    #pragma unroll 2
    for (int e = 0; e < 64; e += 4) {
        const u64 w0 = *(const u64*)(wbase + (size_t)(e + 0) * 256);
        const u64 w1 = *(const u64*)(wbase + (size_t)(e + 1) * 256);
        const u64 w2 = *(const u64*)(wbase + (size_t)(e + 2) * 256);
        const u64 w3 = *(const u64*)(wbase + (size_t)(e + 3) * 256);
        const float* dsr = &ds[(dq * 4) * 64 + e];
        #pragma unroll
        for (int d = 0; d < 4; d++) {
            const float* r = dsr + d * 64;
            acc[d] = ffma2(pack2(r[0], r[0]), w0, acc[d]);
            acc[d] = ffma2(pack2(r[1], r[1]), w1, acc[d]);
            acc[d] = ffma2(pack2(r[2], r[2]), w2, acc[d]);
            acc[d] = ffma2(pack2(r[3], r[3]), w3, acc[d]);
        }
    }
    #pragma unroll
    for (int d = 0; d < 4; d++) {
        float o0, o1; unpack2(acc[d], o0, o1);
        const int dgg = h * 64 + dg * 8 + dq * 4 + d;
        size_t r0 = ((size_t)b * 256 + 2 * p) * 512;
        W2s[r0 + dgg]       = __float2half_rn(o0);
        W2s[r0 + 512 + dgg] = __float2half_rn(o1);
    }
}

// ---------------- launch ----------------
extern "C" void kernel_launch(void* const* d_in, const int* in_sizes, int n_in,
                              void* d_out, int out_size) {
    const float* x     = (const float*)d_in[0];
    const float* z     = (const float*)d_in[1];
    const float* x_pos = (const float*)d_in[2];
    const float* z_pos = (const float*)d_in[3];
    const float* Wq    = (const float*)d_in[4];
    const float* Wkv   = (const float*)d_in[5];
    const float* Wout  = (const float*)d_in[6];
    const float* bout  = (const float*)d_in[7];
    float* out = (float*)d_out;

    float *dotp, *zrot, *xrot;
    __half *kvs, *z2, *x2, *wkv2, *wq2, *q2, *w2s;
    cudaGetSymbolAddress((void**)&kvs,  g_kvs);
    cudaGetSymbolAddress((void**)&dotp, g_dotp);
    cudaGetSymbolAddress((void**)&z2,   g_z2);
    cudaGetSymbolAddress((void**)&x2,   g_x2);
    cudaGetSymbolAddress((void**)&wkv2, g_wkv2);
    cudaGetSymbolAddress((void**)&wq2,  g_wq2);
    cudaGetSymbolAddress((void**)&q2,   g_q2);
    cudaGetSymbolAddress((void**)&w2s,  g_w2s);
    cudaGetSymbolAddress((void**)&zrot, g_zrot);
    cudaGetSymbolAddress((void**)&xrot, g_xrot);

    static cudaStream_t s2 = nullptr;
    static cudaEvent_t evRoot = nullptr, evKV = nullptr, evQ = nullptr;
    if (!s2) {
        cudaStreamCreateWithFlags(&s2, cudaStreamNonBlocking);
        cudaEventCreateWithFlags(&evRoot, cudaEventDisableTiming);
        cudaEventCreateWithFlags(&evKV, cudaEventDisableTiming);
        cudaEventCreateWithFlags(&evQ, cudaEventDisableTiming);
        cudaFuncSetAttribute(gemm_kv,  cudaFuncAttributeMaxDynamicSharedMemorySize, GSMEM);
        cudaFuncSetAttribute(gemm_q,   cudaFuncAttributeMaxDynamicSharedMemorySize, GSMEM);
        cudaFuncSetAttribute(gemm_epi, cudaFuncAttributeMaxDynamicSharedMemorySize, GSMEM);
        cudaFuncSetAttribute(dots_pure, cudaFuncAttributeMaxDynamicSharedMemorySize, DSM_BYTES);
    }

    cudaEventRecord(evRoot, 0);
    cudaStreamWaitEvent(s2, evRoot, 0);

    // prep halves concurrent: blocks = 8192 data + Nw/32*8 weight tiles + 2048 rot
    prep_part<<<8192 + 256 + 2048, 256>>>(z, Wkv, z2, wkv2, 1024, z_pos, zrot);
    prep_part<<<8192 + 128 + 2048, 256, 0, s2>>>(x, Wq, x2, wq2, 512, x_pos, xrot);

    // kv GEMM on main stream
    gemm_kv<<<dim3(8, 256), 256, GSMEM>>>(z2, wkv2, kvs, zrot);
    cudaEventRecord(evKV, 0);

    // q GEMM on side stream after kv -> overlaps dots+w2k
    cudaStreamWaitEvent(s2, evKV, 0);
    gemm_q<<<dim3(4, 256), 256, GSMEM, s2>>>(x2, wq2, q2, xrot);
    cudaEventRecord(evQ, s2);

    // dots + w2k on main stream
    dots_pure<<<dim3(NSPLIT, 64), 256, DSM_BYTES>>>(kvs, dotp);
    w2k<<<dim3(64, 8), 256>>>(dotp, Wout, w2s);

    // join
    cudaStreamWaitEvent(0, evQ, 0);
    gemm_epi<<<dim3(2, 32, BATCH), 256, GSMEM>>>(q2, w2s, out, bout);
}